// round 2
// baseline (speedup 1.0000x reference)
#include <cuda_runtime.h>

// ===================== problem constants =====================
#define B_      32
#define N_      3137
#define C_      768
#define H_      12
#define D_      64
#define SCALE_  0.125f          // 1/sqrt(64)
#define C4_     192             // C_/4

// split-KV config
#define SPLITS  23
#define CHUNK   137             // ceil(3137/23)
#define TT_     32              // tokens per tile
#define XS_STRIDE 772           // 768 + 4 pad floats (odd float4 stride -> conflict-free)
#define K2_THREADS 384

typedef unsigned long long u64;
struct __align__(16) U64x2 { u64 a, b; };

// ===================== device scratch =====================
__device__ float g_qs[B_][C_];                       // SCALE*(q_w x0 + q_b)
__device__ float g_s [B_][H_][C_];                   // s vectors
__device__ float g_m [B_][SPLITS][H_];
__device__ float g_l [B_][SPLITS][H_];
__device__ float g_y [B_][SPLITS][H_][C_];           // unnormalized partial y

__device__ __forceinline__ float dot4(float4 a, float4 b) {
    return a.x*b.x + a.y*b.y + a.z*b.z + a.w*b.w;
}

// packed dual-fp32 helpers (sm_100a f32x2 pipe)
__device__ __forceinline__ u64 fma2(u64 a, u64 b, u64 c) {
    u64 d;
    asm("fma.rn.f32x2 %0, %1, %2, %3;" : "=l"(d) : "l"(a), "l"(b), "l"(c));
    return d;
}
__device__ __forceinline__ u64 mul2(u64 a, u64 b) {
    u64 d;
    asm("mul.rn.f32x2 %0, %1, %2;" : "=l"(d) : "l"(a), "l"(b));
    return d;
}
__device__ __forceinline__ u64 pack2(float p) {
    u64 d; unsigned u = __float_as_uint(p);
    asm("mov.b64 %0, {%1, %1};" : "=l"(d) : "r"(u));
    return d;
}
__device__ __forceinline__ float hsum2(u64 v) {
    float lo = __uint_as_float((unsigned)(v & 0xffffffffull));
    float hi = __uint_as_float((unsigned)(v >> 32));
    return lo + hi;
}

// ===================== K1a: q vectors (per batch) =====================
// qs[b][hd] = SCALE * (q_b[hd] + sum_c q_w[hd][c] * x[b,0,c])
__global__ void k_q(const float* __restrict__ x,
                    const float* __restrict__ q_w,
                    const float* __restrict__ q_b) {
    __shared__ float x0[C_];
    int b = blockIdx.x, tid = threadIdx.x;
    for (int i = tid; i < C_; i += 256)
        x0[i] = x[(size_t)b * N_ * C_ + i];
    __syncthreads();
    int w = tid >> 5, lane = tid & 31;
    const float4* x04 = (const float4*)x0;
    for (int o = w; o < C_; o += 8) {
        const float4* qr = (const float4*)(q_w + (size_t)o * C_);
        float s = 0.f;
        #pragma unroll
        for (int k = 0; k < 6; k++)
            s += dot4(qr[lane + 32*k], x04[lane + 32*k]);
        #pragma unroll
        for (int off = 16; off; off >>= 1)
            s += __shfl_xor_sync(0xffffffffu, s, off);
        if (lane == 0) g_qs[b][o] = SCALE_ * (s + q_b[o]);
    }
}

// ===================== K1b: s vectors =====================
// s[b][h][c] = sum_d kv_w[h*64+d][c] * qs[b][h*64+d]
__global__ void k_s(const float* __restrict__ kv_w) {
    __shared__ float qs[C_];
    int p = blockIdx.x, b = blockIdx.y, tid = threadIdx.x;
    for (int i = tid; i < C_; i += 256) qs[i] = g_qs[b][i];
    __syncthreads();
    float* gs = &g_s[b][0][0];
    int lo = p * 1152, hi = lo + 1152;   // 8 * 1152 = 9216 = H_*C_
    for (int idx = lo + tid; idx < hi; idx += 256) {
        int h = idx / C_, c = idx - h * C_;
        const float* kr = kv_w + (size_t)(h * 64) * C_ + c;
        const float* qh = qs + h * 64;
        float acc = 0.f;
        #pragma unroll 8
        for (int d = 0; d < 64; d++)
            acc = fmaf(kr[(size_t)d * C_], qh[d], acc);
        gs[idx] = acc;
    }
}

// ===================== K2: main streaming attention =====================
// grid (SPLITS, B_), 384 threads, ~145KB dynamic smem, online softmax.
// Both phases use the same warp role: head-quad hg = w%3, c-quarter cs = w/3.
// Phase B keeps 4 heads x 3 u64 (24 regs) of y accumulator per thread.
__global__ __launch_bounds__(K2_THREADS, 1)
void k_attn(const float* __restrict__ x) {
    extern __shared__ float sm[];
    float* xs   = sm;                        // 32 * 772
    float* s_sm = sm + 32 * XS_STRIDE;       // 9216
    float* pr   = s_sm + H_ * C_;            // 12*32*4 partial logits
    float* lgT  = pr + 1536;                 // [12][32] logits transposed
    float* p_sm = lgT + 384;                 // [32][12] softmax weights
    float* m_sm = p_sm + 384;                // [12]
    float* l_sm = m_sm + H_;                 // [12]
    float* a_sm = l_sm + H_;                 // [12] alpha

    int sp = blockIdx.x, b = blockIdx.y;
    int tid = threadIdx.x, w = tid >> 5, lane = tid & 31;
    int n0 = sp * CHUNK;
    int n1 = min(N_, n0 + CHUNK);

    // load s into smem (float4, coalesced)
    {
        const float4* gs4 = (const float4*)&g_s[b][0][0];
        float4* s4 = (float4*)s_sm;
        for (int i = tid; i < H_ * C4_; i += K2_THREADS) s4[i] = gs4[i];
    }
    if (tid < H_) { m_sm[tid] = -1e30f; l_sm[tid] = 0.f; }

    // shared warp role for phases A and B
    int hg = w % 3, cs = w / 3;    // heads [4*hg, 4*hg+4), c-quarter cs

    u64 y[4][3];
    #pragma unroll
    for (int j = 0; j < 4; j++)
        #pragma unroll
        for (int i = 0; i < 3; i++) y[j][i] = 0ull;   // bits of {0.f,0.f}

    for (int t0 = n0; t0 < n1; t0 += TT_) {
        int TTl = min(TT_, n1 - t0);
        __syncthreads();   // previous tile fully consumed; s_sm ready on 1st iter

        // ---- load x tile (streaming, zero-fill partial tiles) ----
        for (int f = tid; f < 32 * C4_; f += K2_THREADS) {
            int t = f / C4_, c4 = f - t * C4_;
            float4 v = make_float4(0.f, 0.f, 0.f, 0.f);
            if (t < TTl)
                v = __ldcs(((const float4*)x) + ((size_t)b * N_ + (t0 + t)) * C4_ + c4);
            *(float4*)(xs + t * XS_STRIDE + 4 * c4) = v;
        }
        __syncthreads();

        // ---- phase A: partial logits (packed f32x2), lane = token ----
        {
            u64 acc[4] = {0ull, 0ull, 0ull, 0ull};
            const char* xp = (const char*)(xs + lane * XS_STRIDE) + 16 * (48 * cs);
            const char* sb = (const char*)(s_sm + 4 * hg * C_) + 16 * (48 * cs);
            #pragma unroll 4
            for (int c4 = 0; c4 < 48; c4++) {
                U64x2 xv = *(const U64x2*)(xp);
                #pragma unroll
                for (int j = 0; j < 4; j++) {
                    U64x2 sv = *(const U64x2*)(sb + (size_t)j * (C_ * 4));
                    acc[j] = fma2(xv.a, sv.a, acc[j]);
                    acc[j] = fma2(xv.b, sv.b, acc[j]);
                }
                xp += 16; sb += 16;
            }
            ((float4*)pr)[w * 32 + lane] =
                make_float4(hsum2(acc[0]), hsum2(acc[1]), hsum2(acc[2]), hsum2(acc[3]));
        }
        __syncthreads();

        // ---- reduce partials over the 4 c-quarters ----
        {
            int h = tid % 12, t = tid / 12;           // 384 = 32*12 exactly
            int hg2 = h >> 2, j = h & 3;
            float v = 0.f;
            #pragma unroll
            for (int c = 0; c < 4; c++)
                v += pr[((hg2 + 3 * c) * 32 + t) * 4 + j];
            lgT[h * 32 + t] = (t < TTl) ? v : -1e30f;
        }
        __syncthreads();

        // ---- online softmax update: warp w handles head w ----
        if (w < H_) {
            float v = lgT[w * 32 + lane];
            float mt = v;
            #pragma unroll
            for (int off = 16; off; off >>= 1)
                mt = fmaxf(mt, __shfl_xor_sync(0xffffffffu, mt, off));
            float mo = m_sm[w];
            float mn = fmaxf(mo, mt);
            float pv = (lane < TTl) ? __expf(v - mn) : 0.f;
            float lt = pv;
            #pragma unroll
            for (int off = 16; off; off >>= 1)
                lt += __shfl_xor_sync(0xffffffffu, lt, off);
            p_sm[lane * 12 + w] = pv;
            if (lane == 0) {
                float al = __expf(mo - mn);
                l_sm[w] = al * l_sm[w] + lt;
                m_sm[w] = mn;
                a_sm[w] = al;
            }
        }
        __syncthreads();

        // ---- phase B: y[h] = alpha*y[h] + sum_t p[t,h]*x[t]  (packed f32x2) ----
        {
            #pragma unroll
            for (int j = 0; j < 4; j++) {
                u64 alp = pack2(a_sm[4 * hg + j]);
                #pragma unroll
                for (int i = 0; i < 3; i++) y[j][i] = mul2(y[j][i], alp);
            }
            float pv0 = p_sm[lane * 12 + 4 * hg + 0];
            float pv1 = p_sm[lane * 12 + 4 * hg + 1];
            float pv2 = p_sm[lane * 12 + 4 * hg + 2];
            float pv3 = p_sm[lane * 12 + 4 * hg + 3];
            const char* xbase = (const char*)xs + 8 * (cs * 96 + lane);
            #pragma unroll 4
            for (int t = 0; t < TT_; t++) {    // p==0 and xs==0 beyond TTl
                u64 p0 = pack2(__shfl_sync(0xffffffffu, pv0, t));
                u64 p1 = pack2(__shfl_sync(0xffffffffu, pv1, t));
                u64 p2 = pack2(__shfl_sync(0xffffffffu, pv2, t));
                u64 p3 = pack2(__shfl_sync(0xffffffffu, pv3, t));
                const char* xr = xbase + (size_t)t * (XS_STRIDE * 4);
                #pragma unroll
                for (int i = 0; i < 3; i++) {
                    u64 xv = *(const u64*)(xr + 8 * (32 * i));
                    y[0][i] = fma2(p0, xv, y[0][i]);
                    y[1][i] = fma2(p1, xv, y[1][i]);
                    y[2][i] = fma2(p2, xv, y[2][i]);
                    y[3][i] = fma2(p3, xv, y[3][i]);
                }
            }
        }
    }
    __syncthreads();  // make last softmax writes visible to tid<12 readers

    if (tid < H_) {
        g_m[b][sp][tid] = m_sm[tid];
        g_l[b][sp][tid] = l_sm[tid];
    }
    {
        #pragma unroll
        for (int j = 0; j < 4; j++) {
            u64* gy = (u64*)&g_y[b][sp][4 * hg + j][0];
            #pragma unroll
            for (int i = 0; i < 3; i++)
                gy[cs * 96 + lane + 32 * i] = y[j][i];
        }
    }
}

// ===================== K3: combine splits + V-proj + out-proj =====================
__global__ void k_out(const float* __restrict__ kv_w,
                      const float* __restrict__ kv_b,
                      const float* __restrict__ proj_w,
                      const float* __restrict__ proj_b,
                      float* __restrict__ out) {
    __shared__ float y_sm[H_ * C_];     // 36 KB
    __shared__ float cls_sm[C_];
    __shared__ float ws[SPLITS * H_];
    __shared__ float linv[H_];
    int b = blockIdx.x, tid = threadIdx.x, w = tid >> 5, lane = tid & 31;

    if (tid < H_) {
        float mg = -1e30f;
        for (int s = 0; s < SPLITS; s++) mg = fmaxf(mg, g_m[b][s][tid]);
        float L = 0.f;
        for (int s = 0; s < SPLITS; s++) {
            float e = __expf(g_m[b][s][tid] - mg);
            ws[s * H_ + tid] = e;
            L += g_l[b][s][tid] * e;
        }
        linv[tid] = 1.f / L;
    }
    __syncthreads();

    for (int idx = tid; idx < H_ * C_; idx += 256) {
        int h = idx / C_;
        float acc = 0.f;
        #pragma unroll 1
        for (int s = 0; s < SPLITS; s++)
            acc = fmaf(ws[s * H_ + h], (&g_y[b][s][0][0])[idx], acc);
        y_sm[idx] = acc * linv[h];
    }
    __syncthreads();

    // cls[o] = kv_b[C+o] + sum_c kv_w[C+o][c] * y[h(o)][c]
    const float4* y4 = (const float4*)y_sm;
    for (int o = w; o < C_; o += 8) {
        int h = o >> 6;
        const float4* kr = (const float4*)(kv_w + (size_t)(C_ + o) * C_);
        float s = 0.f;
        #pragma unroll
        for (int k = 0; k < 6; k++)
            s += dot4(kr[lane + 32*k], y4[h * C4_ + lane + 32*k]);
        #pragma unroll
        for (int off = 16; off; off >>= 1)
            s += __shfl_xor_sync(0xffffffffu, s, off);
        if (lane == 0) cls_sm[o] = s + kv_b[C_ + o];
    }
    __syncthreads();

    const float4* c4p = (const float4*)cls_sm;
    for (int o = w; o < C_; o += 8) {
        const float4* prw = (const float4*)(proj_w + (size_t)o * C_);
        float s = 0.f;
        #pragma unroll
        for (int k = 0; k < 6; k++)
            s += dot4(prw[lane + 32*k], c4p[lane + 32*k]);
        #pragma unroll
        for (int off = 16; off; off >>= 1)
            s += __shfl_xor_sync(0xffffffffu, s, off);
        if (lane == 0) out[b * C_ + o] = s + proj_b[o];
    }
}

// ===================== launch =====================
extern "C" void kernel_launch(void* const* d_in, const int* in_sizes, int n_in,
                              void* d_out, int out_size) {
    const float* x      = (const float*)d_in[0];
    const float* kv_w   = (const float*)d_in[1];
    const float* kv_b   = (const float*)d_in[2];
    const float* q_w    = (const float*)d_in[3];
    const float* q_b    = (const float*)d_in[4];
    const float* proj_w = (const float*)d_in[5];
    const float* proj_b = (const float*)d_in[6];
    float* out = (float*)d_out;

    size_t smem = (size_t)(32 * XS_STRIDE + H_ * C_ + 1536 + 384 + 384 + 3 * H_)
                  * sizeof(float);   // 145,040 B
    cudaFuncSetAttribute(k_attn, cudaFuncAttributeMaxDynamicSharedMemorySize,
                         (int)smem);

    k_q  <<<B_, 256>>>(x, q_w, q_b);
    k_s  <<<dim3(8, B_), 256>>>(kv_w);
    k_attn<<<dim3(SPLITS, B_), K2_THREADS, smem>>>(x);
    k_out<<<B_, 256>>>(kv_w, kv_b, proj_w, proj_b, out);
}

// round 3
// speedup vs baseline: 1.7918x; 1.7918x over previous
#include <cuda_runtime.h>

// ===================== problem constants =====================
#define B_      32
#define N_      3137
#define C_      768
#define H_      12
#define D_      64
#define SCALE_  0.125f          // 1/sqrt(64)
#define C4_     192             // C_/4

// split-KV config
#define SPLITS  23
#define CHUNK   137             // ceil(3137/23)
#define TT_     32              // tokens per tile
#define XS_STRIDE 772           // 768 + 4 pad floats (odd float4 stride -> conflict-free)
#define K2_THREADS 384

typedef unsigned long long u64;
struct __align__(16) U64x2 { u64 a, b; };

// ===================== device scratch =====================
__device__ float g_qs[B_][C_];                       // SCALE*(q_w x0 + q_b)
__device__ float g_s [B_][H_][C_];                   // s vectors
__device__ float g_m [B_][SPLITS][H_];
__device__ float g_l [B_][SPLITS][H_];
__device__ float g_y [B_][SPLITS][H_][C_];           // unnormalized partial y
__device__ float g_yc[B_][H_][C_];                   // combined, normalized y
__device__ float g_cls[B_][C_];                      // v-projected cls embedding

__device__ __forceinline__ float dot4(float4 a, float4 b) {
    return a.x*b.x + a.y*b.y + a.z*b.z + a.w*b.w;
}

// packed dual-fp32 helpers (sm_100a f32x2 pipe)
__device__ __forceinline__ u64 fma2(u64 a, u64 b, u64 c) {
    u64 d;
    asm("fma.rn.f32x2 %0, %1, %2, %3;" : "=l"(d) : "l"(a), "l"(b), "l"(c));
    return d;
}
__device__ __forceinline__ u64 mul2(u64 a, u64 b) {
    u64 d;
    asm("mul.rn.f32x2 %0, %1, %2;" : "=l"(d) : "l"(a), "l"(b));
    return d;
}
__device__ __forceinline__ u64 pack2(float p) {
    u64 d; unsigned u = __float_as_uint(p);
    asm("mov.b64 %0, {%1, %1};" : "=l"(d) : "r"(u));
    return d;
}
__device__ __forceinline__ float hsum2(u64 v) {
    float lo = __uint_as_float((unsigned)(v & 0xffffffffull));
    float hi = __uint_as_float((unsigned)(v >> 32));
    return lo + hi;
}

// ===================== K1a: q vectors (per batch) =====================
__global__ void k_q(const float* __restrict__ x,
                    const float* __restrict__ q_w,
                    const float* __restrict__ q_b) {
    __shared__ float x0[C_];
    int b = blockIdx.x, tid = threadIdx.x;
    for (int i = tid; i < C_; i += 256)
        x0[i] = x[(size_t)b * N_ * C_ + i];
    __syncthreads();
    int w = tid >> 5, lane = tid & 31;
    const float4* x04 = (const float4*)x0;
    for (int o = w; o < C_; o += 8) {
        const float4* qr = (const float4*)(q_w + (size_t)o * C_);
        float s = 0.f;
        #pragma unroll
        for (int k = 0; k < 6; k++)
            s += dot4(qr[lane + 32*k], x04[lane + 32*k]);
        #pragma unroll
        for (int off = 16; off; off >>= 1)
            s += __shfl_xor_sync(0xffffffffu, s, off);
        if (lane == 0) g_qs[b][o] = SCALE_ * (s + q_b[o]);
    }
}

// ===================== K1b: s vectors =====================
// s[b][h][c] = sum_d kv_w[h*64+d][c] * qs[b][h*64+d]
__global__ void k_s(const float* __restrict__ kv_w) {
    __shared__ float qs[C_];
    int p = blockIdx.x, b = blockIdx.y, tid = threadIdx.x;
    for (int i = tid; i < C_; i += 256) qs[i] = g_qs[b][i];
    __syncthreads();
    float* gs = &g_s[b][0][0];
    int lo = p * 1152, hi = lo + 1152;   // 8 * 1152 = 9216 = H_*C_
    for (int idx = lo + tid; idx < hi; idx += 256) {
        int h = idx / C_, c = idx - h * C_;
        const float* kr = kv_w + (size_t)(h * 64) * C_ + c;
        const float* qh = qs + h * 64;
        float acc = 0.f;
        #pragma unroll 8
        for (int d = 0; d < 64; d++)
            acc = fmaf(kr[(size_t)d * C_], qh[d], acc);
        gs[idx] = acc;
    }
}

// ===================== K2: main streaming attention =====================
// grid (SPLITS, B_), 384 threads, ~145KB dynamic smem, online softmax.
// Both phases use the same warp role: head-quad hg = w%3, c-quarter cs = w/3.
__global__ __launch_bounds__(K2_THREADS, 1)
void k_attn(const float* __restrict__ x) {
    extern __shared__ float sm[];
    float* xs   = sm;                        // 32 * 772
    float* s_sm = sm + 32 * XS_STRIDE;       // 9216
    float* pr   = s_sm + H_ * C_;            // 12*32*4 partial logits
    float* lgT  = pr + 1536;                 // [12][32] logits transposed
    float* p_sm = lgT + 384;                 // [32][12] softmax weights
    float* m_sm = p_sm + 384;                // [12]
    float* l_sm = m_sm + H_;                 // [12]
    float* a_sm = l_sm + H_;                 // [12] alpha

    int sp = blockIdx.x, b = blockIdx.y;
    int tid = threadIdx.x, w = tid >> 5, lane = tid & 31;
    int n0 = sp * CHUNK;
    int n1 = min(N_, n0 + CHUNK);

    {
        const float4* gs4 = (const float4*)&g_s[b][0][0];
        float4* s4 = (float4*)s_sm;
        for (int i = tid; i < H_ * C4_; i += K2_THREADS) s4[i] = gs4[i];
    }
    if (tid < H_) { m_sm[tid] = -1e30f; l_sm[tid] = 0.f; }

    int hg = w % 3, cs = w / 3;    // heads [4*hg, 4*hg+4), c-quarter cs

    u64 y[4][3];
    #pragma unroll
    for (int j = 0; j < 4; j++)
        #pragma unroll
        for (int i = 0; i < 3; i++) y[j][i] = 0ull;

    for (int t0 = n0; t0 < n1; t0 += TT_) {
        int TTl = min(TT_, n1 - t0);
        __syncthreads();

        // ---- load x tile (streaming, zero-fill partial tiles) ----
        for (int f = tid; f < 32 * C4_; f += K2_THREADS) {
            int t = f / C4_, c4 = f - t * C4_;
            float4 v = make_float4(0.f, 0.f, 0.f, 0.f);
            if (t < TTl)
                v = __ldcs(((const float4*)x) + ((size_t)b * N_ + (t0 + t)) * C4_ + c4);
            *(float4*)(xs + t * XS_STRIDE + 4 * c4) = v;
        }
        __syncthreads();

        // ---- phase A: partial logits (packed f32x2), lane = token ----
        {
            u64 acc[4] = {0ull, 0ull, 0ull, 0ull};
            const char* xp = (const char*)(xs + lane * XS_STRIDE) + 16 * (48 * cs);
            const char* sb = (const char*)(s_sm + 4 * hg * C_) + 16 * (48 * cs);
            #pragma unroll 4
            for (int c4 = 0; c4 < 48; c4++) {
                U64x2 xv = *(const U64x2*)(xp);
                #pragma unroll
                for (int j = 0; j < 4; j++) {
                    U64x2 sv = *(const U64x2*)(sb + (size_t)j * (C_ * 4));
                    acc[j] = fma2(xv.a, sv.a, acc[j]);
                    acc[j] = fma2(xv.b, sv.b, acc[j]);
                }
                xp += 16; sb += 16;
            }
            ((float4*)pr)[w * 32 + lane] =
                make_float4(hsum2(acc[0]), hsum2(acc[1]), hsum2(acc[2]), hsum2(acc[3]));
        }
        __syncthreads();

        // ---- reduce partials over the 4 c-quarters ----
        {
            int h = tid % 12, t = tid / 12;
            int hg2 = h >> 2, j = h & 3;
            float v = 0.f;
            #pragma unroll
            for (int c = 0; c < 4; c++)
                v += pr[((hg2 + 3 * c) * 32 + t) * 4 + j];
            lgT[h * 32 + t] = (t < TTl) ? v : -1e30f;
        }
        __syncthreads();

        // ---- online softmax: warp w handles head w ----
        if (w < H_) {
            float v = lgT[w * 32 + lane];
            float mt = v;
            #pragma unroll
            for (int off = 16; off; off >>= 1)
                mt = fmaxf(mt, __shfl_xor_sync(0xffffffffu, mt, off));
            float mo = m_sm[w];
            float mn = fmaxf(mo, mt);
            float pv = (lane < TTl) ? __expf(v - mn) : 0.f;
            float lt = pv;
            #pragma unroll
            for (int off = 16; off; off >>= 1)
                lt += __shfl_xor_sync(0xffffffffu, lt, off);
            p_sm[lane * 12 + w] = pv;
            if (lane == 0) {
                float al = __expf(mo - mn);
                l_sm[w] = al * l_sm[w] + lt;
                m_sm[w] = mn;
                a_sm[w] = al;
            }
        }
        __syncthreads();

        // ---- phase B: y[h] = alpha*y[h] + sum_t p[t,h]*x[t]  (packed f32x2) ----
        {
            #pragma unroll
            for (int j = 0; j < 4; j++) {
                u64 alp = pack2(a_sm[4 * hg + j]);
                #pragma unroll
                for (int i = 0; i < 3; i++) y[j][i] = mul2(y[j][i], alp);
            }
            float pv0 = p_sm[lane * 12 + 4 * hg + 0];
            float pv1 = p_sm[lane * 12 + 4 * hg + 1];
            float pv2 = p_sm[lane * 12 + 4 * hg + 2];
            float pv3 = p_sm[lane * 12 + 4 * hg + 3];
            const char* xbase = (const char*)xs + 8 * (cs * 96 + lane);
            #pragma unroll 4
            for (int t = 0; t < TT_; t++) {
                u64 p0 = pack2(__shfl_sync(0xffffffffu, pv0, t));
                u64 p1 = pack2(__shfl_sync(0xffffffffu, pv1, t));
                u64 p2 = pack2(__shfl_sync(0xffffffffu, pv2, t));
                u64 p3 = pack2(__shfl_sync(0xffffffffu, pv3, t));
                const char* xr = xbase + (size_t)t * (XS_STRIDE * 4);
                #pragma unroll
                for (int i = 0; i < 3; i++) {
                    u64 xv = *(const u64*)(xr + 8 * (32 * i));
                    y[0][i] = fma2(p0, xv, y[0][i]);
                    y[1][i] = fma2(p1, xv, y[1][i]);
                    y[2][i] = fma2(p2, xv, y[2][i]);
                    y[3][i] = fma2(p3, xv, y[3][i]);
                }
            }
        }
    }
    __syncthreads();

    if (tid < H_) {
        g_m[b][sp][tid] = m_sm[tid];
        g_l[b][sp][tid] = l_sm[tid];
    }
    {
        #pragma unroll
        for (int j = 0; j < 4; j++) {
            u64* gy = (u64*)&g_y[b][sp][4 * hg + j][0];
            #pragma unroll
            for (int i = 0; i < 3; i++)
                gy[cs * 96 + lane + 32 * i] = y[j][i];
        }
    }
}

// ===================== K3a: combine split partials =====================
// grid (H_, B_), 256 threads: g_yc[b][h][:] = norm'd sum over splits.
__global__ void k_combine() {
    int h = blockIdx.x, b = blockIdx.y, tid = threadIdx.x;
    int lane = tid & 31;
    __shared__ float ws[SPLITS];
    __shared__ float linv_s;
    if (tid < 32) {
        float m = (lane < SPLITS) ? g_m[b][lane][h] : -1e30f;
        float mg = m;
        #pragma unroll
        for (int off = 16; off; off >>= 1)
            mg = fmaxf(mg, __shfl_xor_sync(0xffffffffu, mg, off));
        float e = (lane < SPLITS) ? __expf(m - mg) : 0.f;
        float le = (lane < SPLITS) ? g_l[b][lane][h] * e : 0.f;
        #pragma unroll
        for (int off = 16; off; off >>= 1)
            le += __shfl_xor_sync(0xffffffffu, le, off);
        if (lane < SPLITS) ws[lane] = e;
        if (lane == 0) linv_s = 1.f / le;
    }
    __syncthreads();
    // 768 floats / 256 threads = 3 per thread; splits loop is independent loads
    for (int c = tid; c < C_; c += 256) {
        float acc = 0.f;
        #pragma unroll 1
        for (int s = 0; s < SPLITS; s++)
            acc = fmaf(ws[s], g_y[b][s][h][c], acc);
        g_yc[b][h][c] = acc * linv_s;
    }
}

// ===================== K3b: cls = W_v y + b_v  =====================
// grid (H_, B_): block x handles outputs o in [64x, 64x+64) -> all same head x.
__global__ void k_cls(const float* __restrict__ kv_w,
                      const float* __restrict__ kv_b) {
    int hx = blockIdx.x, b = blockIdx.y, tid = threadIdx.x;
    int w = tid >> 5, lane = tid & 31;
    __shared__ float y_s[C_];
    for (int i = tid; i < C_; i += 256) y_s[i] = g_yc[b][hx][i];
    __syncthreads();
    const float4* y4 = (const float4*)y_s;
    for (int oo = w; oo < 64; oo += 8) {
        int o = hx * 64 + oo;
        const float4* kr = (const float4*)(kv_w + (size_t)(C_ + o) * C_);
        float s = 0.f;
        #pragma unroll
        for (int k = 0; k < 6; k++)
            s += dot4(kr[lane + 32*k], y4[lane + 32*k]);
        #pragma unroll
        for (int off = 16; off; off >>= 1)
            s += __shfl_xor_sync(0xffffffffu, s, off);
        if (lane == 0) g_cls[b][o] = s + kv_b[C_ + o];
    }
}

// ===================== K3c: out = W_p cls + b_p =====================
// grid (12, B_): block x handles outputs o in [64x, 64x+64).
__global__ void k_proj(const float* __restrict__ proj_w,
                       const float* __restrict__ proj_b,
                       float* __restrict__ out) {
    int xblk = blockIdx.x, b = blockIdx.y, tid = threadIdx.x;
    int w = tid >> 5, lane = tid & 31;
    __shared__ float c_s[C_];
    for (int i = tid; i < C_; i += 256) c_s[i] = g_cls[b][i];
    __syncthreads();
    const float4* c4 = (const float4*)c_s;
    for (int oo = w; oo < 64; oo += 8) {
        int o = xblk * 64 + oo;
        const float4* prw = (const float4*)(proj_w + (size_t)o * C_);
        float s = 0.f;
        #pragma unroll
        for (int k = 0; k < 6; k++)
            s += dot4(prw[lane + 32*k], c4[lane + 32*k]);
        #pragma unroll
        for (int off = 16; off; off >>= 1)
            s += __shfl_xor_sync(0xffffffffu, s, off);
        if (lane == 0) out[b * C_ + o] = s + proj_b[o];
    }
}

// ===================== launch =====================
extern "C" void kernel_launch(void* const* d_in, const int* in_sizes, int n_in,
                              void* d_out, int out_size) {
    const float* x      = (const float*)d_in[0];
    const float* kv_w   = (const float*)d_in[1];
    const float* kv_b   = (const float*)d_in[2];
    const float* q_w    = (const float*)d_in[3];
    const float* q_b    = (const float*)d_in[4];
    const float* proj_w = (const float*)d_in[5];
    const float* proj_b = (const float*)d_in[6];
    float* out = (float*)d_out;

    size_t smem = (size_t)(32 * XS_STRIDE + H_ * C_ + 1536 + 384 + 384 + 3 * H_)
                  * sizeof(float);   // 145,040 B
    cudaFuncSetAttribute(k_attn, cudaFuncAttributeMaxDynamicSharedMemorySize,
                         (int)smem);

    k_q      <<<B_, 256>>>(x, q_w, q_b);
    k_s      <<<dim3(8, B_), 256>>>(kv_w);
    k_attn   <<<dim3(SPLITS, B_), K2_THREADS, smem>>>(x);
    k_combine<<<dim3(H_, B_), 256>>>();
    k_cls    <<<dim3(H_, B_), 256>>>(kv_w, kv_b);
    k_proj   <<<dim3(H_, B_), 256>>>(proj_w, proj_b, out);
}

// round 4
// speedup vs baseline: 2.2629x; 1.2629x over previous
#include <cuda_runtime.h>

// ===================== problem constants =====================
#define B_      32
#define N_      3137
#define C_      768
#define H_      12
#define D_      64
#define SCALE_  0.125f          // 1/sqrt(64)
#define C4_     192             // C_/4

// split-KV config
#define SPLITS  23
#define CHUNK   137             // ceil(3137/23)
#define TT_     28              // tokens per tile (double-buffered)
#define XS_STRIDE 772           // 768 + 4 pad floats (odd float4 stride -> conflict-free)
#define K2_THREADS 384
#define LD_PER_THREAD 14        // TT_*C4_/K2_THREADS = 28*192/384

typedef unsigned long long u64;
struct __align__(16) U64x2 { u64 a, b; };

// ===================== device scratch =====================
__device__ float g_qs[B_][C_];                       // SCALE*(q_w x0 + q_b)
__device__ float g_s [B_][H_][C_];                   // s vectors
__device__ float g_m [B_][SPLITS][H_];
__device__ float g_l [B_][SPLITS][H_];
__device__ float g_y [B_][SPLITS][H_][C_];           // unnormalized partial y
__device__ float g_yc[B_][H_][C_];                   // combined, normalized y
__device__ float g_cls[B_][C_];                      // v-projected cls embedding

__device__ __forceinline__ float dot4(float4 a, float4 b) {
    return a.x*b.x + a.y*b.y + a.z*b.z + a.w*b.w;
}

// packed dual-fp32 helpers (sm_100a f32x2 pipe)
__device__ __forceinline__ u64 fma2(u64 a, u64 b, u64 c) {
    u64 d;
    asm("fma.rn.f32x2 %0, %1, %2, %3;" : "=l"(d) : "l"(a), "l"(b), "l"(c));
    return d;
}
__device__ __forceinline__ u64 mul2(u64 a, u64 b) {
    u64 d;
    asm("mul.rn.f32x2 %0, %1, %2;" : "=l"(d) : "l"(a), "l"(b));
    return d;
}
__device__ __forceinline__ u64 pack2(float p) {
    u64 d; unsigned u = __float_as_uint(p);
    asm("mov.b64 %0, {%1, %1};" : "=l"(d) : "r"(u));
    return d;
}
__device__ __forceinline__ float hsum2(u64 v) {
    float lo = __uint_as_float((unsigned)(v & 0xffffffffull));
    float hi = __uint_as_float((unsigned)(v >> 32));
    return lo + hi;
}

// cp.async 16B (LDGSTS), L2-targeted
__device__ __forceinline__ void cpa16(void* smem_dst, const void* gsrc) {
    unsigned saddr = (unsigned)__cvta_generic_to_shared(smem_dst);
    asm volatile("cp.async.cg.shared.global [%0], [%1], 16;"
                 :: "r"(saddr), "l"(gsrc) : "memory");
}

// ===================== K1a: q vectors =====================
// grid (4, B_): block p covers outputs [192p, 192p+192)
__global__ void k_q(const float* __restrict__ x,
                    const float* __restrict__ q_w,
                    const float* __restrict__ q_b) {
    __shared__ float x0[C_];
    int p = blockIdx.x, b = blockIdx.y, tid = threadIdx.x;
    for (int i = tid; i < C_; i += 256)
        x0[i] = x[(size_t)b * N_ * C_ + i];
    __syncthreads();
    int w = tid >> 5, lane = tid & 31;
    const float4* x04 = (const float4*)x0;
    for (int oo = w; oo < 192; oo += 8) {
        int o = p * 192 + oo;
        const float4* qr = (const float4*)(q_w + (size_t)o * C_);
        float s = 0.f;
        #pragma unroll
        for (int k = 0; k < 6; k++)
            s += dot4(qr[lane + 32*k], x04[lane + 32*k]);
        #pragma unroll
        for (int off = 16; off; off >>= 1)
            s += __shfl_xor_sync(0xffffffffu, s, off);
        if (lane == 0) g_qs[b][o] = SCALE_ * (s + q_b[o]);
    }
}

// ===================== K1b: s vectors =====================
// s[b][h][c] = sum_d kv_w[h*64+d][c] * qs[b][h*64+d]
__global__ void k_s(const float* __restrict__ kv_w) {
    __shared__ float qs[C_];
    int p = blockIdx.x, b = blockIdx.y, tid = threadIdx.x;
    for (int i = tid; i < C_; i += 256) qs[i] = g_qs[b][i];
    __syncthreads();
    float* gs = &g_s[b][0][0];
    int lo = p * 1152, hi = lo + 1152;   // 8 * 1152 = 9216 = H_*C_
    for (int idx = lo + tid; idx < hi; idx += 256) {
        int h = idx / C_, c = idx - h * C_;
        const float* kr = kv_w + (size_t)(h * 64) * C_ + c;
        const float* qh = qs + h * 64;
        float acc = 0.f;
        #pragma unroll 8
        for (int d = 0; d < 64; d++)
            acc = fmaf(kr[(size_t)d * C_], qh[d], acc);
        gs[idx] = acc;
    }
}

// ===================== K2: main streaming attention =====================
// grid (SPLITS, B_), 384 threads, ~219KB smem, cp.async double-buffered tiles.
__device__ __forceinline__ void issue_tile(const float* __restrict__ x,
                                           float* xsb, int b, int t0,
                                           int TTl, int tid) {
    const float4* xg = (const float4*)x + ((size_t)b * N_ + t0) * C4_;
    #pragma unroll
    for (int k = 0; k < LD_PER_THREAD; k++) {
        int f = tid + k * K2_THREADS;
        int t = f / C4_, c4 = f - t * C4_;
        if (t < TTl)
            cpa16(xsb + t * XS_STRIDE + 4 * c4, xg + (size_t)t * C4_ + c4);
    }
    asm volatile("cp.async.commit_group;" ::: "memory");
}

__global__ __launch_bounds__(K2_THREADS, 1)
void k_attn(const float* __restrict__ x) {
    extern __shared__ float sm[];
    float* xs   = sm;                                 // 2 * 28 * 772
    float* s_sm = sm + 2 * TT_ * XS_STRIDE;           // 9216
    float* pr   = s_sm + H_ * C_;                     // 12*32*4 partial logits
    float* lgT  = pr + 1536;                          // [12][32]
    float* p_sm = lgT + 384;                          // [32][12]
    float* m_sm = p_sm + 384;                         // [12]
    float* l_sm = m_sm + H_;                          // [12]
    float* a_sm = l_sm + H_;                          // [12]

    int sp = blockIdx.x, b = blockIdx.y;
    int tid = threadIdx.x, w = tid >> 5, lane = tid & 31;
    int n0 = sp * CHUNK;
    int n1 = min(N_, n0 + CHUNK);
    int nT = (n1 - n0 + TT_ - 1) / TT_;

    // preload tile 0 into buffer 0 (start DRAM traffic ASAP)
    issue_tile(x, xs, b, n0, min(TT_, n1 - n0), tid);

    // load s into smem (float4, coalesced)
    {
        const float4* gs4 = (const float4*)&g_s[b][0][0];
        float4* s4 = (float4*)s_sm;
        for (int i = tid; i < H_ * C4_; i += K2_THREADS) s4[i] = gs4[i];
    }
    if (tid < H_) { m_sm[tid] = -1e30f; l_sm[tid] = 0.f; }

    int hg = w % 3, cs = w / 3;    // heads [4*hg, 4*hg+4), c-quarter cs

    u64 y[4][3];
    #pragma unroll
    for (int j = 0; j < 4; j++)
        #pragma unroll
        for (int i = 0; i < 3; i++) y[j][i] = 0ull;

    for (int it = 0; it < nT; it++) {
        int t0 = n0 + it * TT_;
        int TTl = min(TT_, n1 - t0);
        float* xsb = xs + (it & 1) * (TT_ * XS_STRIDE);

        // issue next tile into the other buffer (safe: prev trailing sync passed)
        if (it + 1 < nT) {
            issue_tile(x, xs + ((it + 1) & 1) * (TT_ * XS_STRIDE),
                       b, t0 + TT_, min(TT_, n1 - t0 - TT_), tid);
            asm volatile("cp.async.wait_group 1;" ::: "memory");
        } else {
            asm volatile("cp.async.wait_group 0;" ::: "memory");
        }
        __syncthreads();   // tile `it` resident; all warps aligned

        // ---- phase A: partial logits (packed f32x2), lane = token ----
        {
            u64 acc[4] = {0ull, 0ull, 0ull, 0ull};
            const char* xp = (const char*)(xsb + lane * XS_STRIDE) + 16 * (48 * cs);
            const char* sb = (const char*)(s_sm + 4 * hg * C_) + 16 * (48 * cs);
            #pragma unroll 4
            for (int c4 = 0; c4 < 48; c4++) {
                U64x2 xv = *(const U64x2*)(xp);
                #pragma unroll
                for (int j = 0; j < 4; j++) {
                    U64x2 sv = *(const U64x2*)(sb + (size_t)j * (C_ * 4));
                    acc[j] = fma2(xv.a, sv.a, acc[j]);
                    acc[j] = fma2(xv.b, sv.b, acc[j]);
                }
                xp += 16; sb += 16;
            }
            ((float4*)pr)[w * 32 + lane] =
                make_float4(hsum2(acc[0]), hsum2(acc[1]), hsum2(acc[2]), hsum2(acc[3]));
        }
        __syncthreads();

        // ---- reduce partials over the 4 c-quarters ----
        {
            int h = tid % 12, t = tid / 12;
            int hg2 = h >> 2, j = h & 3;
            float v = 0.f;
            #pragma unroll
            for (int c = 0; c < 4; c++)
                v += pr[((hg2 + 3 * c) * 32 + t) * 4 + j];
            lgT[h * 32 + t] = (t < TTl) ? v : -1e30f;
        }
        __syncthreads();

        // ---- online softmax: warp w handles head w ----
        if (w < H_) {
            float v = lgT[w * 32 + lane];
            float mt = v;
            #pragma unroll
            for (int off = 16; off; off >>= 1)
                mt = fmaxf(mt, __shfl_xor_sync(0xffffffffu, mt, off));
            float mo = m_sm[w];
            float mn = fmaxf(mo, mt);
            float pv = (lane < TTl) ? __expf(v - mn) : 0.f;
            float lt = pv;
            #pragma unroll
            for (int off = 16; off; off >>= 1)
                lt += __shfl_xor_sync(0xffffffffu, lt, off);
            p_sm[lane * 12 + w] = pv;
            if (lane == 0) {
                float al = __expf(mo - mn);
                l_sm[w] = al * l_sm[w] + lt;
                m_sm[w] = mn;
                a_sm[w] = al;
            }
        }
        __syncthreads();

        // ---- phase B: y[h] = alpha*y[h] + sum_t p[t,h]*x[t]  (packed f32x2) ----
        {
            #pragma unroll
            for (int j = 0; j < 4; j++) {
                u64 alp = pack2(a_sm[4 * hg + j]);
                #pragma unroll
                for (int i = 0; i < 3; i++) y[j][i] = mul2(y[j][i], alp);
            }
            float pv0 = p_sm[lane * 12 + 4 * hg + 0];
            float pv1 = p_sm[lane * 12 + 4 * hg + 1];
            float pv2 = p_sm[lane * 12 + 4 * hg + 2];
            float pv3 = p_sm[lane * 12 + 4 * hg + 3];
            const char* xbase = (const char*)xsb + 8 * (cs * 96 + lane);
            #pragma unroll 4
            for (int t = 0; t < TT_; t++) {    // p==0 beyond TTl
                u64 p0 = pack2(__shfl_sync(0xffffffffu, pv0, t));
                u64 p1 = pack2(__shfl_sync(0xffffffffu, pv1, t));
                u64 p2 = pack2(__shfl_sync(0xffffffffu, pv2, t));
                u64 p3 = pack2(__shfl_sync(0xffffffffu, pv3, t));
                const char* xr = xbase + (size_t)t * (XS_STRIDE * 4);
                #pragma unroll
                for (int i = 0; i < 3; i++) {
                    u64 xv = *(const u64*)(xr + 8 * (32 * i));
                    y[0][i] = fma2(p0, xv, y[0][i]);
                    y[1][i] = fma2(p1, xv, y[1][i]);
                    y[2][i] = fma2(p2, xv, y[2][i]);
                    y[3][i] = fma2(p3, xv, y[3][i]);
                }
            }
        }
        __syncthreads();   // trailing: buffer fully consumed before reuse
    }

    if (tid < H_) {
        g_m[b][sp][tid] = m_sm[tid];
        g_l[b][sp][tid] = l_sm[tid];
    }
    {
        #pragma unroll
        for (int j = 0; j < 4; j++) {
            u64* gy = (u64*)&g_y[b][sp][4 * hg + j][0];
            #pragma unroll
            for (int i = 0; i < 3; i++)
                gy[cs * 96 + lane + 32 * i] = y[j][i];
        }
    }
}

// ===================== K3a: combine split partials =====================
// grid (H_, B_), 192 threads: thread = one float4 column, 23 independent loads.
__global__ void k_combine() {
    int h = blockIdx.x, b = blockIdx.y, tid = threadIdx.x;
    int lane = tid & 31;
    __shared__ float ws[SPLITS];
    __shared__ float linv_s;
    if (tid < 32) {
        float m = (lane < SPLITS) ? g_m[b][lane][h] : -1e30f;
        float mg = m;
        #pragma unroll
        for (int off = 16; off; off >>= 1)
            mg = fmaxf(mg, __shfl_xor_sync(0xffffffffu, mg, off));
        float e = (lane < SPLITS) ? __expf(m - mg) : 0.f;
        float le = (lane < SPLITS) ? g_l[b][lane][h] * e : 0.f;
        #pragma unroll
        for (int off = 16; off; off >>= 1)
            le += __shfl_xor_sync(0xffffffffu, le, off);
        if (lane < SPLITS) ws[lane] = e;
        if (lane == 0) linv_s = 1.f / le;
    }
    __syncthreads();
    float4 acc = make_float4(0.f, 0.f, 0.f, 0.f);
    #pragma unroll
    for (int s = 0; s < SPLITS; s++) {
        float4 v = ((const float4*)&g_y[b][s][h][0])[tid];
        float wv = ws[s];
        acc.x = fmaf(wv, v.x, acc.x);
        acc.y = fmaf(wv, v.y, acc.y);
        acc.z = fmaf(wv, v.z, acc.z);
        acc.w = fmaf(wv, v.w, acc.w);
    }
    float li = linv_s;
    ((float4*)&g_yc[b][h][0])[tid] =
        make_float4(acc.x * li, acc.y * li, acc.z * li, acc.w * li);
}

// ===================== K3b: cls = W_v y + b_v =====================
__global__ void k_cls(const float* __restrict__ kv_w,
                      const float* __restrict__ kv_b) {
    int hx = blockIdx.x, b = blockIdx.y, tid = threadIdx.x;
    int w = tid >> 5, lane = tid & 31;
    __shared__ float y_s[C_];
    for (int i = tid; i < C_; i += 256) y_s[i] = g_yc[b][hx][i];
    __syncthreads();
    const float4* y4 = (const float4*)y_s;
    for (int oo = w; oo < 64; oo += 8) {
        int o = hx * 64 + oo;
        const float4* kr = (const float4*)(kv_w + (size_t)(C_ + o) * C_);
        float s = 0.f;
        #pragma unroll
        for (int k = 0; k < 6; k++)
            s += dot4(kr[lane + 32*k], y4[lane + 32*k]);
        #pragma unroll
        for (int off = 16; off; off >>= 1)
            s += __shfl_xor_sync(0xffffffffu, s, off);
        if (lane == 0) g_cls[b][o] = s + kv_b[C_ + o];
    }
}

// ===================== K3c: out = W_p cls + b_p =====================
__global__ void k_proj(const float* __restrict__ proj_w,
                       const float* __restrict__ proj_b,
                       float* __restrict__ out) {
    int xblk = blockIdx.x, b = blockIdx.y, tid = threadIdx.x;
    int w = tid >> 5, lane = tid & 31;
    __shared__ float c_s[C_];
    for (int i = tid; i < C_; i += 256) c_s[i] = g_cls[b][i];
    __syncthreads();
    const float4* c4 = (const float4*)c_s;
    for (int oo = w; oo < 64; oo += 8) {
        int o = xblk * 64 + oo;
        const float4* prw = (const float4*)(proj_w + (size_t)o * C_);
        float s = 0.f;
        #pragma unroll
        for (int k = 0; k < 6; k++)
            s += dot4(prw[lane + 32*k], c4[lane + 32*k]);
        #pragma unroll
        for (int off = 16; off; off >>= 1)
            s += __shfl_xor_sync(0xffffffffu, s, off);
        if (lane == 0) out[b * C_ + o] = s + proj_b[o];
    }
}

// ===================== launch =====================
extern "C" void kernel_launch(void* const* d_in, const int* in_sizes, int n_in,
                              void* d_out, int out_size) {
    const float* x      = (const float*)d_in[0];
    const float* kv_w   = (const float*)d_in[1];
    const float* kv_b   = (const float*)d_in[2];
    const float* q_w    = (const float*)d_in[3];
    const float* q_b    = (const float*)d_in[4];
    const float* proj_w = (const float*)d_in[5];
    const float* proj_b = (const float*)d_in[6];
    float* out = (float*)d_out;

    size_t smem = (size_t)(2 * TT_ * XS_STRIDE + H_ * C_ + 1536 + 384 + 384 + 3 * H_)
                  * sizeof(float);   // 219,152 B
    cudaFuncSetAttribute(k_attn, cudaFuncAttributeMaxDynamicSharedMemorySize,
                         (int)smem);

    k_q      <<<dim3(4, B_), 256>>>(x, q_w, q_b);
    k_s      <<<dim3(8, B_), 256>>>(kv_w);
    k_attn   <<<dim3(SPLITS, B_), K2_THREADS, smem>>>(x);
    k_combine<<<dim3(H_, B_), 192>>>();
    k_cls    <<<dim3(H_, B_), 256>>>(kv_w, kv_b);
    k_proj   <<<dim3(H_, B_), 256>>>(proj_w, proj_b, out);
}